// round 10
// baseline (speedup 1.0000x reference)
#include <cuda_runtime.h>
#include <cuda_fp16.h>
#include <cstdint>

// Problem constants
#define NN      8192
#define DD      128
#define BTN     64                 // CTA tile rows (n)
#define BTM     128                // CTA tile cols (m)
#define NTN     (NN / BTN)         // 128
#define NTM     (NN / BTM)         // 64
#define NUNITS  (NTN * NTM)        // 8192
#define NCTA    296                // 2 CTAs per SM
#define SCALE   50.0f

// SMEM geometry: padded row stride 272 bytes (136 fp16)
#define SROW    272
#define TA      (BTN * SROW)       // 17408
#define TBB     (BTM * SROW)       // 34816
#define OFF_A     0
#define OFF_B(buf)  (TA + (buf) * TBB)
#define SMEM_BYTES (TA + 2 * TBB)  // 87040 per CTA (x2 = 174080 per SM)

// Static device scratch
__device__ __half g_ts_h[NN * DD];
__device__ __half g_sq_h[NN * DD];
__device__ float  g_ts_f[NN * DD];   // fp32 normalized (exact diag)
__device__ float  g_sq_f[NN * DD];
__device__ float  g_rowsum[NN];
__device__ double g_acc[2];
__device__ unsigned int g_cnt;

// ---------------- PTX helpers ----------------
__device__ __forceinline__ void cp16(uint32_t saddr, const void* g) {
    asm volatile("cp.async.cg.shared.global [%0], [%1], 16;" :: "r"(saddr), "l"(g));
}
__device__ __forceinline__ void cp_commit() { asm volatile("cp.async.commit_group;"); }
__device__ __forceinline__ void cp_wait0()  { asm volatile("cp.async.wait_group 0;"); }
__device__ __forceinline__ void cp_wait1()  { asm volatile("cp.async.wait_group 1;"); }

__device__ __forceinline__ void ldsm4(uint32_t a, uint32_t& r0, uint32_t& r1,
                                      uint32_t& r2, uint32_t& r3) {
    asm volatile("ldmatrix.sync.aligned.m8n8.x4.shared.b16 {%0,%1,%2,%3}, [%4];"
                 : "=r"(r0), "=r"(r1), "=r"(r2), "=r"(r3) : "r"(a));
}
// fp16-accumulate HMMA
__device__ __forceinline__ void mma16816h(uint32_t* c, const uint32_t* a,
                                          uint32_t b0, uint32_t b1) {
    asm volatile("mma.sync.aligned.m16n8k16.row.col.f16.f16.f16.f16 "
                 "{%0,%1}, {%2,%3,%4,%5}, {%6,%7}, {%0,%1};"
                 : "+r"(c[0]), "+r"(c[1])
                 : "r"(a[0]), "r"(a[1]), "r"(a[2]), "r"(a[3]), "r"(b0), "r"(b1));
}
__device__ __forceinline__ float2 h2_to_f2(uint32_t u) {
    float2 r;
    asm("{\n\t.reg .f16 h0, h1;\n\t"
        "mov.b32 {h0, h1}, %2;\n\t"
        "cvt.f32.f16 %0, h0;\n\t"
        "cvt.f32.f16 %1, h1;\n\t}" : "=f"(r.x), "=f"(r.y) : "r"(u));
    return r;
}

// ---------------- kernel 1: normalize -> fp16 (GEMM) + fp32 (diag) ----------------
__global__ void __launch_bounds__(256) k_norm(const float* __restrict__ ts,
                                              const float* __restrict__ sq) {
    const int tid = threadIdx.x;
    if (blockIdx.x < 8) {   // zero accumulators
        reinterpret_cast<float4*>(g_rowsum)[blockIdx.x * 256 + tid] =
            make_float4(0.f, 0.f, 0.f, 0.f);
        if (blockIdx.x == 0 && tid == 0) {
            g_acc[0] = 0.0; g_acc[1] = 0.0; g_cnt = 0u;
        }
    }
    int gwarp = blockIdx.x * 8 + (tid >> 5);
    int lane  = tid & 31;
    if (gwarp >= 2 * NN) return;
    const bool is_ts = gwarp < NN;
    const int  n     = is_ts ? gwarp : gwarp - NN;
    const float* src = is_ts ? ts : sq;
    __half* dh = is_ts ? g_ts_h : g_sq_h;
    float*  df = is_ts ? g_ts_f : g_sq_f;

    float4 v = reinterpret_cast<const float4*>(src + (size_t)n * DD)[lane];
    float ss = v.x * v.x + v.y * v.y + v.z * v.z + v.w * v.w;
#pragma unroll
    for (int o = 16; o; o >>= 1) ss += __shfl_xor_sync(0xffffffffu, ss, o);
    float inv = 1.0f / fmaxf(sqrtf(ss), 1e-12f);

    float x[4] = {v.x * inv, v.y * inv, v.z * inv, v.w * inv};
    size_t e = (size_t)n * DD + lane * 4;
    *reinterpret_cast<__half2*>(dh + e)     = __floats2half2_rn(x[0], x[1]);
    *reinterpret_cast<__half2*>(dh + e + 2) = __floats2half2_rn(x[2], x[3]);
    *reinterpret_cast<float4*>(df + e)      = make_float4(x[0], x[1], x[2], x[3]);
}

// ---------------- tile loaders (128 threads) ----------------
__device__ __forceinline__ void load_A_async(uint32_t s_dst, const __half* g,
                                             int row0, int tid) {
#pragma unroll
    for (int it = 0; it < 8; ++it) {
        int ch  = tid + it * 128;       // 0..1023 chunks (64 rows x 16)
        int r   = ch >> 4;
        int c16 = ch & 15;
        cp16(s_dst + (uint32_t)(r * SROW + c16 * 16),
             g + (size_t)(row0 + r) * DD + c16 * 8);
    }
}
__device__ __forceinline__ void load_B_async(uint32_t s_dst, const __half* g,
                                             int row0, int tid) {
#pragma unroll
    for (int it = 0; it < 16; ++it) {
        int ch  = tid + it * 128;       // 0..2047 chunks (128 rows x 16)
        int r   = ch >> 4;
        int c16 = ch & 15;
        cp16(s_dst + (uint32_t)(r * SROW + c16 * 16),
             g + (size_t)(row0 + r) * DD + c16 * 8);
    }
}

// process 1/8 of the previous unit's accumulators
#define PREV_CHUNK(kk)                                                         \
    {                                                                          \
        const int pi = (kk) >> 1, pc0 = ((kk) & 1) * 2;                        \
        _Pragma("unroll")                                                      \
        for (int cb = 0; cb < 2; ++cb) {                                       \
            float2 lo = h2_to_f2(accP[pi][pc0 + cb][0]);                       \
            float2 hi = h2_to_f2(accP[pi][pc0 + cb][1]);                       \
            sums[pi][0] += __expf(fmaf(lo.x, SCALE, -SCALE));                  \
            sums[pi][0] += __expf(fmaf(lo.y, SCALE, -SCALE));                  \
            sums[pi][1] += __expf(fmaf(hi.x, SCALE, -SCALE));                  \
            sums[pi][1] += __expf(fmaf(hi.y, SCALE, -SCALE));                  \
        }                                                                      \
    }

// ---------------- kernel 2: 2-CTA/SM fp16 mma GEMM, pipelined epilogue ----------------
__global__ void __launch_bounds__(128, 2) k_main() {
    extern __shared__ char sh[];
    const uint32_t tb = (uint32_t)__cvta_generic_to_shared(sh);

    const int tid  = threadIdx.x;
    const int lane = tid & 31;
    const int wx   = tid >> 5;         // m block (32 cols each); all warps share 64 rows
    const int quad = lane >> 3, rw = lane & 7;
    const int qr   = lane >> 2, qc = lane & 3;

    const uint32_t offA = (uint32_t)(((quad & 1) * 8 + rw) * SROW + (quad >> 1) * 16);
    const uint32_t offB = (uint32_t)(((quad >> 1) * 8 + rw) * SROW + (quad & 1) * 16);
    const uint32_t bRow = (uint32_t)(wx * 32 * SROW);

    const int c  = blockIdx.x;
    const int u0 = (c * NUNITS) / NCTA;
    const int u1 = ((c + 1) * NUNITS) / NCTA;

    // previous-unit accumulators (half2); -2.0h -> exp(50*(-2)-50) = 0
    uint32_t accP[4][4][2];
#pragma unroll
    for (int i = 0; i < 4; ++i)
#pragma unroll
        for (int cb = 0; cb < 4; ++cb) {
            accP[i][cb][0] = 0xC000C000u; accP[i][cb][1] = 0xC000C000u;
        }
    float sums[4][2];
#pragma unroll
    for (int i = 0; i < 4; ++i) { sums[i][0] = 0.f; sums[i][1] = 0.f; }

    int cur_n = -1;
    int n_prev = u0 >> 6;              // harmless target for the zero flush

    for (int u = u0; u < u1; ++u) {
        const int n   = u >> 6;        // 64 m-tiles per n
        const int m   = u & 63;
        const int buf = u & 1;

        if (n != cur_n) {
            __syncthreads();
            load_A_async(tb + OFF_A, g_ts_h, n * BTN, tid);
            load_B_async(tb + OFF_B(buf), g_sq_h, m * BTM, tid);
            cp_commit();
            cp_wait0();
            cur_n = n;
        }
        if (u + 1 < u1 && ((u + 1) >> 6) == n) {
            load_B_async(tb + OFF_B(buf ^ 1), g_sq_h, ((u + 1) & 63) * BTM, tid);
        }
        cp_commit();
        cp_wait1();
        __syncthreads();

        const uint32_t aP = tb + OFF_A + offA;
        const uint32_t bP = tb + OFF_B(buf) + bRow + offB;

        uint32_t accC[4][4][2];
#pragma unroll
        for (int i = 0; i < 4; ++i)
#pragma unroll
            for (int cb = 0; cb < 4; ++cb) { accC[i][cb][0] = 0u; accC[i][cb][1] = 0u; }

#pragma unroll
        for (int kk = 0; kk < 8; ++kk) {
            const uint32_t ko = (uint32_t)(kk * 32);
            uint32_t a[4][4];
#pragma unroll
            for (int i = 0; i < 4; ++i)
                ldsm4(aP + i * (16 * SROW) + ko, a[i][0], a[i][1], a[i][2], a[i][3]);
#pragma unroll
            for (int j = 0; j < 2; ++j) {
                uint32_t b0, b1, b2, b3;
                ldsm4(bP + j * (16 * SROW) + ko, b0, b1, b2, b3);
#pragma unroll
                for (int i = 0; i < 4; ++i) {
                    mma16816h(accC[i][2 * j],     a[i], b0, b1);
                    mma16816h(accC[i][2 * j + 1], a[i], b2, b3);
                }
            }
            PREV_CHUNK(kk);            // previous unit's exp in the MMA shadow
        }

        // flush previous unit's row sums
#pragma unroll
        for (int i = 0; i < 4; ++i) {
            float s0 = sums[i][0], s1 = sums[i][1];
            s0 += __shfl_xor_sync(0xffffffffu, s0, 1);
            s0 += __shfl_xor_sync(0xffffffffu, s0, 2);
            s1 += __shfl_xor_sync(0xffffffffu, s1, 1);
            s1 += __shfl_xor_sync(0xffffffffu, s1, 2);
            if (qc == 0) {
                int r = n_prev * BTN + i * 16 + qr;
                atomicAdd(&g_rowsum[r], s0);
                atomicAdd(&g_rowsum[r + 8], s1);
            }
            sums[i][0] = 0.f; sums[i][1] = 0.f;
        }
        n_prev = n;
#pragma unroll
        for (int i = 0; i < 4; ++i)
#pragma unroll
            for (int cb = 0; cb < 4; ++cb) {
                accP[i][cb][0] = accC[i][cb][0];
                accP[i][cb][1] = accC[i][cb][1];
            }
        __syncthreads();
    }

    // drain: last unit's accumulators
#pragma unroll
    for (int kk = 0; kk < 8; ++kk) PREV_CHUNK(kk);
#pragma unroll
    for (int i = 0; i < 4; ++i) {
        float s0 = sums[i][0], s1 = sums[i][1];
        s0 += __shfl_xor_sync(0xffffffffu, s0, 1);
        s0 += __shfl_xor_sync(0xffffffffu, s0, 2);
        s1 += __shfl_xor_sync(0xffffffffu, s1, 1);
        s1 += __shfl_xor_sync(0xffffffffu, s1, 2);
        if (qc == 0) {
            int r = n_prev * BTN + i * 16 + qr;
            atomicAdd(&g_rowsum[r], s0);
            atomicAdd(&g_rowsum[r + 8], s1);
        }
    }
}

// ---------------- kernel 3: exact diag + lse + masked loss (+ fused div) ----------------
__global__ void __launch_bounds__(256) k_final(const int* __restrict__ pmask,
                                               float* __restrict__ out) {
    __shared__ double s_loss[256];
    __shared__ float  s_pm[256];
    __shared__ int    s_last;
    const int tid = threadIdx.x;
    const int n   = blockIdx.x * 256 + tid;

    float d = 0.f;
    const size_t base = (size_t)n * DD;
#pragma unroll 8
    for (int k = 0; k < DD; ++k)
        d += g_ts_f[base + k] * g_sq_f[base + k];
    d *= SCALE;

    float lse = SCALE + logf(g_rowsum[n]);
    float pm  = (float)pmask[n];

    s_loss[tid] = (double)(pm * (d - lse));
    s_pm[tid]   = pm;
    __syncthreads();
    for (int o = 128; o; o >>= 1) {
        if (tid < o) { s_loss[tid] += s_loss[tid + o]; s_pm[tid] += s_pm[tid + o]; }
        __syncthreads();
    }
    if (tid == 0) {
        atomicAdd(&g_acc[0], s_loss[0]);
        atomicAdd(&g_acc[1], (double)s_pm[0]);
        __threadfence();
        unsigned int v = atomicAdd(&g_cnt, 1u);
        s_last = (v == (unsigned int)(gridDim.x - 1)) ? 1 : 0;
    }
    __syncthreads();
    if (s_last && tid == 0)
        out[0] = (float)(-g_acc[0] / (g_acc[1] + 1e-6));
}

extern "C" void kernel_launch(void* const* d_in, const int* in_sizes, int n_in,
                              void* d_out, int out_size) {
    const float* ts = (const float*)d_in[0];
    const float* sq = (const float*)d_in[1];
    const int*   pm = (const int*)d_in[3];
    float* out = (float*)d_out;

    cudaFuncSetAttribute(k_main, cudaFuncAttributeMaxDynamicSharedMemorySize, SMEM_BYTES);

    k_norm<<<2048, 256>>>(ts, sq);
    k_main<<<NCTA, 128, SMEM_BYTES>>>();
    k_final<<<NN / 256, 256>>>(pm, out);
}

// round 11
// speedup vs baseline: 1.1043x; 1.1043x over previous
#include <cuda_runtime.h>
#include <cuda_fp16.h>
#include <cstdint>

// Problem constants
#define NN      8192
#define DD      128
#define BTN     256                // CTA tile rows (n)
#define BTM     128                // CTA tile cols (m)
#define NTN     (NN / BTN)         // 32
#define NTM     (NN / BTM)         // 64
#define NUNITS  (NTN * NTM)        // 2048
#define NCTA    148
#define SCALE   50.0f

// SMEM geometry: padded row stride 272 bytes (136 fp16)
#define SROW    272
#define TA      (BTN * SROW)       // 69632
#define TBB     (BTM * SROW)       // 34816
#define OFF_A     0
#define OFF_B(buf)  (TA + (buf) * TBB)
#define SMEM_BYTES (TA + 2 * TBB)  // 139264

// Static device scratch
__device__ __half g_ts_h[NN * DD];
__device__ __half g_sq_h[NN * DD];
__device__ float  g_ts_f[NN * DD];   // fp32 normalized (exact diag)
__device__ float  g_sq_f[NN * DD];
__device__ float  g_rowsum[NN];
__device__ double g_acc[2];
__device__ unsigned int g_cnt;

// ---------------- PTX helpers ----------------
__device__ __forceinline__ void cp16(uint32_t saddr, const void* g) {
    asm volatile("cp.async.cg.shared.global [%0], [%1], 16;" :: "r"(saddr), "l"(g));
}
__device__ __forceinline__ void cp_commit() { asm volatile("cp.async.commit_group;"); }
__device__ __forceinline__ void cp_wait0()  { asm volatile("cp.async.wait_group 0;"); }
__device__ __forceinline__ void cp_wait1()  { asm volatile("cp.async.wait_group 1;"); }

__device__ __forceinline__ void ldsm4(uint32_t a, uint32_t& r0, uint32_t& r1,
                                      uint32_t& r2, uint32_t& r3) {
    asm volatile("ldmatrix.sync.aligned.m8n8.x4.shared.b16 {%0,%1,%2,%3}, [%4];"
                 : "=r"(r0), "=r"(r1), "=r"(r2), "=r"(r3) : "r"(a));
}
// fp16-accumulate HMMA
__device__ __forceinline__ void mma16816h(uint32_t* c, const uint32_t* a,
                                          uint32_t b0, uint32_t b1) {
    asm volatile("mma.sync.aligned.m16n8k16.row.col.f16.f16.f16.f16 "
                 "{%0,%1}, {%2,%3,%4,%5}, {%6,%7}, {%0,%1};"
                 : "+r"(c[0]), "+r"(c[1])
                 : "r"(a[0]), "r"(a[1]), "r"(a[2]), "r"(a[3]), "r"(b0), "r"(b1));
}
__device__ __forceinline__ float2 h2_to_f2(uint32_t u) {
    float2 r;
    asm("{\n\t.reg .f16 h0, h1;\n\t"
        "mov.b32 {h0, h1}, %2;\n\t"
        "cvt.f32.f16 %0, h0;\n\t"
        "cvt.f32.f16 %1, h1;\n\t}" : "=f"(r.x), "=f"(r.y) : "r"(u));
    return r;
}

// ---------------- kernel 1: normalize -> fp16 (GEMM) + fp32 (diag) ----------------
__global__ void __launch_bounds__(256) k_norm(const float* __restrict__ ts,
                                              const float* __restrict__ sq) {
    const int tid = threadIdx.x;
    if (blockIdx.x < 8) {   // zero accumulators
        reinterpret_cast<float4*>(g_rowsum)[blockIdx.x * 256 + tid] =
            make_float4(0.f, 0.f, 0.f, 0.f);
        if (blockIdx.x == 0 && tid == 0) {
            g_acc[0] = 0.0; g_acc[1] = 0.0; g_cnt = 0u;
        }
    }
    int gwarp = blockIdx.x * 8 + (tid >> 5);
    int lane  = tid & 31;
    if (gwarp >= 2 * NN) return;
    const bool is_ts = gwarp < NN;
    const int  n     = is_ts ? gwarp : gwarp - NN;
    const float* src = is_ts ? ts : sq;
    __half* dh = is_ts ? g_ts_h : g_sq_h;
    float*  df = is_ts ? g_ts_f : g_sq_f;

    float4 v = reinterpret_cast<const float4*>(src + (size_t)n * DD)[lane];
    float ss = v.x * v.x + v.y * v.y + v.z * v.z + v.w * v.w;
#pragma unroll
    for (int o = 16; o; o >>= 1) ss += __shfl_xor_sync(0xffffffffu, ss, o);
    float inv = 1.0f / fmaxf(sqrtf(ss), 1e-12f);

    float x[4] = {v.x * inv, v.y * inv, v.z * inv, v.w * inv};
    size_t e = (size_t)n * DD + lane * 4;
    *reinterpret_cast<__half2*>(dh + e)     = __floats2half2_rn(x[0], x[1]);
    *reinterpret_cast<__half2*>(dh + e + 2) = __floats2half2_rn(x[2], x[3]);
    *reinterpret_cast<float4*>(df + e)      = make_float4(x[0], x[1], x[2], x[3]);
}

// ---------------- tile loaders (256 threads) ----------------
__device__ __forceinline__ void load_A_async(uint32_t s_dst, const __half* g,
                                             int row0, int tid) {
#pragma unroll
    for (int it = 0; it < 16; ++it) {
        int ch  = tid + it * 256;       // 0..4095 chunks (256 rows x 16)
        int r   = ch >> 4;
        int c16 = ch & 15;
        cp16(s_dst + (uint32_t)(r * SROW + c16 * 16),
             g + (size_t)(row0 + r) * DD + c16 * 8);
    }
}
__device__ __forceinline__ void load_B_async(uint32_t s_dst, const __half* g,
                                             int row0, int tid) {
#pragma unroll
    for (int it = 0; it < 8; ++it) {
        int ch  = tid + it * 256;       // 0..2047 chunks (128 rows x 16)
        int r   = ch >> 4;
        int c16 = ch & 15;
        cp16(s_dst + (uint32_t)(r * SROW + c16 * 16),
             g + (size_t)(row0 + r) * DD + c16 * 8);
    }
}

// process 1/8 of the previous unit's accumulators: i = kk>>1, 4 col-blocks
#define PREV_CHUNK(kk)                                                         \
    {                                                                          \
        const int pi = (kk) >> 1, pc0 = ((kk) & 1) * 4;                        \
        _Pragma("unroll")                                                      \
        for (int cb = 0; cb < 4; ++cb) {                                       \
            float2 lo = h2_to_f2(accP[pi][pc0 + cb][0]);                       \
            float2 hi = h2_to_f2(accP[pi][pc0 + cb][1]);                       \
            sums[pi][0] += __expf(fmaf(lo.x, SCALE, -SCALE));                  \
            sums[pi][0] += __expf(fmaf(lo.y, SCALE, -SCALE));                  \
            sums[pi][1] += __expf(fmaf(hi.x, SCALE, -SCALE));                  \
            sums[pi][1] += __expf(fmaf(hi.y, SCALE, -SCALE));                  \
        }                                                                      \
    }

// ---------------- kernel 2: persistent fp16 mma GEMM, pipelined epilogue ----------------
__global__ void __launch_bounds__(256, 1) k_main() {
    extern __shared__ char sh[];
    const uint32_t tb = (uint32_t)__cvta_generic_to_shared(sh);

    const int tid  = threadIdx.x;
    const int lane = tid & 31;
    const int wid  = tid >> 5;
    const int wy   = wid >> 1;         // n block (64 rows), 0..3
    const int wx   = wid & 1;          // m block (64 cols), 0..1
    const int quad = lane >> 3, rw = lane & 7;
    const int qr   = lane >> 2, qc = lane & 3;

    const uint32_t offA = (uint32_t)(((quad & 1) * 8 + rw) * SROW + (quad >> 1) * 16);
    const uint32_t offB = (uint32_t)(((quad >> 1) * 8 + rw) * SROW + (quad & 1) * 16);
    const uint32_t aRow = (uint32_t)(wy * 64 * SROW);
    const uint32_t bRow = (uint32_t)(wx * 64 * SROW);

    const int c  = blockIdx.x;
    const int u0 = (c * NUNITS) / NCTA;
    const int u1 = ((c + 1) * NUNITS) / NCTA;

    // previous-unit accumulators (half2); -2.0h -> exp(50*(-2)-50) = 0
    uint32_t accP[4][8][2];
#pragma unroll
    for (int i = 0; i < 4; ++i)
#pragma unroll
        for (int cb = 0; cb < 8; ++cb) {
            accP[i][cb][0] = 0xC000C000u; accP[i][cb][1] = 0xC000C000u;
        }
    float sums[4][2];
#pragma unroll
    for (int i = 0; i < 4; ++i) { sums[i][0] = 0.f; sums[i][1] = 0.f; }

    int cur_n = -1;
    int n_prev = u0 >> 6;              // harmless target for the zero flush

    for (int u = u0; u < u1; ++u) {
        const int n   = u >> 6;        // 64 m-tiles per n-stripe
        const int m   = u & 63;
        const int buf = u & 1;

        if (n != cur_n) {
            __syncthreads();
            load_A_async(tb + OFF_A, g_ts_h, n * BTN, tid);
            load_B_async(tb + OFF_B(buf), g_sq_h, m * BTM, tid);
            cp_commit();
            cp_wait0();
            cur_n = n;
        }
        if (u + 1 < u1 && ((u + 1) >> 6) == n) {
            load_B_async(tb + OFF_B(buf ^ 1), g_sq_h, ((u + 1) & 63) * BTM, tid);
        }
        cp_commit();
        cp_wait1();
        __syncthreads();

        const uint32_t aP = tb + OFF_A + aRow + offA;
        const uint32_t bP = tb + OFF_B(buf) + bRow + offB;

        uint32_t accC[4][8][2];
#pragma unroll
        for (int i = 0; i < 4; ++i)
#pragma unroll
            for (int cb = 0; cb < 8; ++cb) { accC[i][cb][0] = 0u; accC[i][cb][1] = 0u; }

#pragma unroll
        for (int kk = 0; kk < 8; ++kk) {
            const uint32_t ko = (uint32_t)(kk * 32);
            uint32_t a[4][4];
#pragma unroll
            for (int i = 0; i < 4; ++i)
                ldsm4(aP + i * (16 * SROW) + ko, a[i][0], a[i][1], a[i][2], a[i][3]);
#pragma unroll
            for (int j = 0; j < 4; ++j) {
                uint32_t b0, b1, b2, b3;
                ldsm4(bP + j * (16 * SROW) + ko, b0, b1, b2, b3);
#pragma unroll
                for (int i = 0; i < 4; ++i) {
                    mma16816h(accC[i][2 * j],     a[i], b0, b1);
                    mma16816h(accC[i][2 * j + 1], a[i], b2, b3);
                }
            }
            PREV_CHUNK(kk);            // previous unit's exp in the MMA shadow
        }

        // flush previous unit's row sums
#pragma unroll
        for (int i = 0; i < 4; ++i) {
            float s0 = sums[i][0], s1 = sums[i][1];
            s0 += __shfl_xor_sync(0xffffffffu, s0, 1);
            s0 += __shfl_xor_sync(0xffffffffu, s0, 2);
            s1 += __shfl_xor_sync(0xffffffffu, s1, 1);
            s1 += __shfl_xor_sync(0xffffffffu, s1, 2);
            if (qc == 0) {
                int r = n_prev * BTN + wy * 64 + i * 16 + qr;
                atomicAdd(&g_rowsum[r], s0);
                atomicAdd(&g_rowsum[r + 8], s1);
            }
            sums[i][0] = 0.f; sums[i][1] = 0.f;
        }
        n_prev = n;
#pragma unroll
        for (int i = 0; i < 4; ++i)
#pragma unroll
            for (int cb = 0; cb < 8; ++cb) {
                accP[i][cb][0] = accC[i][cb][0];
                accP[i][cb][1] = accC[i][cb][1];
            }
        __syncthreads();
    }

    // drain: last unit's accumulators
#pragma unroll
    for (int kk = 0; kk < 8; ++kk) PREV_CHUNK(kk);
#pragma unroll
    for (int i = 0; i < 4; ++i) {
        float s0 = sums[i][0], s1 = sums[i][1];
        s0 += __shfl_xor_sync(0xffffffffu, s0, 1);
        s0 += __shfl_xor_sync(0xffffffffu, s0, 2);
        s1 += __shfl_xor_sync(0xffffffffu, s1, 1);
        s1 += __shfl_xor_sync(0xffffffffu, s1, 2);
        if (qc == 0) {
            int r = n_prev * BTN + wy * 64 + i * 16 + qr;
            atomicAdd(&g_rowsum[r], s0);
            atomicAdd(&g_rowsum[r + 8], s1);
        }
    }
}

// ---------------- kernel 3: exact diag + lse + masked loss (+ fused div) ----------------
__global__ void __launch_bounds__(256) k_final(const int* __restrict__ pmask,
                                               float* __restrict__ out) {
    __shared__ double s_loss[256];
    __shared__ float  s_pm[256];
    __shared__ int    s_last;
    const int tid = threadIdx.x;
    const int n   = blockIdx.x * 256 + tid;

    float d = 0.f;
    const size_t base = (size_t)n * DD;
#pragma unroll 8
    for (int k = 0; k < DD; ++k)
        d += g_ts_f[base + k] * g_sq_f[base + k];
    d *= SCALE;

    float lse = SCALE + logf(g_rowsum[n]);
    float pm  = (float)pmask[n];

    s_loss[tid] = (double)(pm * (d - lse));
    s_pm[tid]   = pm;
    __syncthreads();
    for (int o = 128; o; o >>= 1) {
        if (tid < o) { s_loss[tid] += s_loss[tid + o]; s_pm[tid] += s_pm[tid + o]; }
        __syncthreads();
    }
    if (tid == 0) {
        atomicAdd(&g_acc[0], s_loss[0]);
        atomicAdd(&g_acc[1], (double)s_pm[0]);
        __threadfence();
        unsigned int v = atomicAdd(&g_cnt, 1u);
        s_last = (v == (unsigned int)(gridDim.x - 1)) ? 1 : 0;
    }
    __syncthreads();
    if (s_last && tid == 0)
        out[0] = (float)(-g_acc[0] / (g_acc[1] + 1e-6));
}

extern "C" void kernel_launch(void* const* d_in, const int* in_sizes, int n_in,
                              void* d_out, int out_size) {
    const float* ts = (const float*)d_in[0];
    const float* sq = (const float*)d_in[1];
    const int*   pm = (const int*)d_in[3];
    float* out = (float*)d_out;

    cudaFuncSetAttribute(k_main, cudaFuncAttributeMaxDynamicSharedMemorySize, SMEM_BYTES);

    k_norm<<<2048, 256>>>(ts, sq);
    k_main<<<NCTA, 256, SMEM_BYTES>>>();
    k_final<<<NN / 256, 256>>>(pm, out);
}

// round 12
// speedup vs baseline: 1.7550x; 1.5893x over previous
#include <cuda_runtime.h>
#include <cuda_fp16.h>
#include <cstdint>

// Problem constants
#define NN      8192
#define DD      128
#define BTN     256                // CTA tile rows (n)
#define BTM     128                // CTA tile cols (m)
#define NTN     (NN / BTN)         // 32
#define NTM     (NN / BTM)         // 64
#define NUNITS  (NTN * NTM)        // 2048
#define NCTA    148
#define SCALE   50.0f

// SMEM geometry: padded row stride 272 bytes (136 fp16)
#define SROW    272
#define TA      (BTN * SROW)       // 69632
#define TBB     (BTM * SROW)       // 34816
#define OFF_A     0
#define OFF_B(buf)  (TA + (buf) * TBB)
#define SMEM_BYTES (TA + 2 * TBB)  // 139264

// Static device scratch
__device__ __half g_ts_h[NN * DD];
__device__ __half g_sq_h[NN * DD];
__device__ float  g_diag[NN];        // 50 * <ts_n, sq_n> (fp32 exact)
__device__ float  g_rowsum[NN];
__device__ double g_acc[2];
__device__ unsigned int g_cnt;

// ---------------- PTX helpers ----------------
__device__ __forceinline__ void cp16(uint32_t saddr, const void* g) {
    asm volatile("cp.async.cg.shared.global [%0], [%1], 16;" :: "r"(saddr), "l"(g));
}
__device__ __forceinline__ void cp_commit() { asm volatile("cp.async.commit_group;"); }
__device__ __forceinline__ void cp_wait0()  { asm volatile("cp.async.wait_group 0;"); }
__device__ __forceinline__ void cp_wait1()  { asm volatile("cp.async.wait_group 1;"); }

__device__ __forceinline__ void ldsm4(uint32_t a, uint32_t& r0, uint32_t& r1,
                                      uint32_t& r2, uint32_t& r3) {
    asm volatile("ldmatrix.sync.aligned.m8n8.x4.shared.b16 {%0,%1,%2,%3}, [%4];"
                 : "=r"(r0), "=r"(r1), "=r"(r2), "=r"(r3) : "r"(a));
}
// fp16-accumulate HMMA
__device__ __forceinline__ void mma16816h(uint32_t* c, const uint32_t* a,
                                          uint32_t b0, uint32_t b1) {
    asm volatile("mma.sync.aligned.m16n8k16.row.col.f16.f16.f16.f16 "
                 "{%0,%1}, {%2,%3,%4,%5}, {%6,%7}, {%0,%1};"
                 : "+r"(c[0]), "+r"(c[1])
                 : "r"(a[0]), "r"(a[1]), "r"(a[2]), "r"(a[3]), "r"(b0), "r"(b1));
}
__device__ __forceinline__ float2 h2_to_f2(uint32_t u) {
    float2 r;
    asm("{\n\t.reg .f16 h0, h1;\n\t"
        "mov.b32 {h0, h1}, %2;\n\t"
        "cvt.f32.f16 %0, h0;\n\t"
        "cvt.f32.f16 %1, h1;\n\t}" : "=f"(r.x), "=f"(r.y) : "r"(u));
    return r;
}

// ---------------- kernel 1: normalize both rows + fp16 out + exact diag ----------------
// One warp handles row n of BOTH matrices. 1024 blocks x 8 warps.
__global__ void __launch_bounds__(256) k_norm(const float* __restrict__ ts,
                                              const float* __restrict__ sq) {
    const int tid = threadIdx.x;
    if (blockIdx.x < 8) {   // zero accumulators
        reinterpret_cast<float4*>(g_rowsum)[blockIdx.x * 256 + tid] =
            make_float4(0.f, 0.f, 0.f, 0.f);
        if (blockIdx.x == 0 && tid == 0) {
            g_acc[0] = 0.0; g_acc[1] = 0.0; g_cnt = 0u;
        }
    }
    const int n    = blockIdx.x * 8 + (tid >> 5);
    const int lane = tid & 31;

    float4 a = reinterpret_cast<const float4*>(ts + (size_t)n * DD)[lane];
    float4 b = reinterpret_cast<const float4*>(sq + (size_t)n * DD)[lane];
    float sst = a.x * a.x + a.y * a.y + a.z * a.z + a.w * a.w;
    float ssq = b.x * b.x + b.y * b.y + b.z * b.z + b.w * b.w;
    float dts = a.x * b.x + a.y * b.y + a.z * b.z + a.w * b.w;
#pragma unroll
    for (int o = 16; o; o >>= 1) {
        sst += __shfl_xor_sync(0xffffffffu, sst, o);
        ssq += __shfl_xor_sync(0xffffffffu, ssq, o);
        dts += __shfl_xor_sync(0xffffffffu, dts, o);
    }
    float inv_t = 1.0f / fmaxf(sqrtf(sst), 1e-12f);
    float inv_s = 1.0f / fmaxf(sqrtf(ssq), 1e-12f);

    size_t e = (size_t)n * DD + lane * 4;
    *reinterpret_cast<__half2*>(g_ts_h + e)     = __floats2half2_rn(a.x * inv_t, a.y * inv_t);
    *reinterpret_cast<__half2*>(g_ts_h + e + 2) = __floats2half2_rn(a.z * inv_t, a.w * inv_t);
    *reinterpret_cast<__half2*>(g_sq_h + e)     = __floats2half2_rn(b.x * inv_s, b.y * inv_s);
    *reinterpret_cast<__half2*>(g_sq_h + e + 2) = __floats2half2_rn(b.z * inv_s, b.w * inv_s);
    if (lane == 0)
        g_diag[n] = dts * inv_t * inv_s * SCALE;
}

// ---------------- tile loaders (256 threads) ----------------
__device__ __forceinline__ void load_A_async(uint32_t s_dst, const __half* g,
                                             int row0, int tid) {
#pragma unroll
    for (int it = 0; it < 16; ++it) {
        int ch  = tid + it * 256;
        int r   = ch >> 4;
        int c16 = ch & 15;
        cp16(s_dst + (uint32_t)(r * SROW + c16 * 16),
             g + (size_t)(row0 + r) * DD + c16 * 8);
    }
}
__device__ __forceinline__ void load_B_async(uint32_t s_dst, const __half* g,
                                             int row0, int tid) {
#pragma unroll
    for (int it = 0; it < 8; ++it) {
        int ch  = tid + it * 256;
        int r   = ch >> 4;
        int c16 = ch & 15;
        cp16(s_dst + (uint32_t)(r * SROW + c16 * 16),
             g + (size_t)(row0 + r) * DD + c16 * 8);
    }
}

// process 1/8 of the previous unit's accumulators
#define PREV_CHUNK(kk)                                                         \
    {                                                                          \
        const int pi = (kk) >> 1, pc0 = ((kk) & 1) * 4;                        \
        _Pragma("unroll")                                                      \
        for (int cb = 0; cb < 4; ++cb) {                                       \
            float2 lo = h2_to_f2(accP[pi][pc0 + cb][0]);                       \
            float2 hi = h2_to_f2(accP[pi][pc0 + cb][1]);                       \
            sums[pi][0] += __expf(fmaf(lo.x, SCALE, -SCALE));                  \
            sums[pi][0] += __expf(fmaf(lo.y, SCALE, -SCALE));                  \
            sums[pi][1] += __expf(fmaf(hi.x, SCALE, -SCALE));                  \
            sums[pi][1] += __expf(fmaf(hi.y, SCALE, -SCALE));                  \
        }                                                                      \
    }

#define FLUSH(nst)                                                             \
    {                                                                          \
        _Pragma("unroll")                                                      \
        for (int i = 0; i < 4; ++i) {                                          \
            float s0 = sums[i][0], s1 = sums[i][1];                            \
            s0 += __shfl_xor_sync(0xffffffffu, s0, 1);                         \
            s0 += __shfl_xor_sync(0xffffffffu, s0, 2);                         \
            s1 += __shfl_xor_sync(0xffffffffu, s1, 1);                         \
            s1 += __shfl_xor_sync(0xffffffffu, s1, 2);                         \
            if (qc == 0) {                                                     \
                int r = (nst) * BTN + wy * 64 + i * 16 + qr;                   \
                atomicAdd(&g_rowsum[r], s0);                                   \
                atomicAdd(&g_rowsum[r + 8], s1);                               \
            }                                                                  \
            sums[i][0] = 0.f; sums[i][1] = 0.f;                                \
        }                                                                      \
    }

// ---------------- kernel 2: persistent fp16 mma GEMM, per-stripe flush ----------------
__global__ void __launch_bounds__(256, 1) k_main() {
    extern __shared__ char sh[];
    const uint32_t tb = (uint32_t)__cvta_generic_to_shared(sh);

    const int tid  = threadIdx.x;
    const int lane = tid & 31;
    const int wid  = tid >> 5;
    const int wy   = wid >> 1;         // n block (64 rows), 0..3
    const int wx   = wid & 1;          // m block (64 cols), 0..1
    const int quad = lane >> 3, rw = lane & 7;
    const int qr   = lane >> 2, qc = lane & 3;

    const uint32_t offA = (uint32_t)(((quad & 1) * 8 + rw) * SROW + (quad >> 1) * 16);
    const uint32_t offB = (uint32_t)(((quad >> 1) * 8 + rw) * SROW + (quad & 1) * 16);
    const uint32_t aRow = (uint32_t)(wy * 64 * SROW);
    const uint32_t bRow = (uint32_t)(wx * 64 * SROW);

    const int c  = blockIdx.x;
    const int u0 = (c * NUNITS) / NCTA;
    const int u1 = ((c + 1) * NUNITS) / NCTA;

    // previous-unit accumulators (half2); -2.0h -> exp(50*(-2)-50) = 0
    uint32_t accP[4][8][2];
#pragma unroll
    for (int i = 0; i < 4; ++i)
#pragma unroll
        for (int cb = 0; cb < 8; ++cb) {
            accP[i][cb][0] = 0xC000C000u; accP[i][cb][1] = 0xC000C000u;
        }
    float sums[4][2];
#pragma unroll
    for (int i = 0; i < 4; ++i) { sums[i][0] = 0.f; sums[i][1] = 0.f; }

    int cur_n = -1;
    int n_acc = -1;                    // stripe of accP contents (-1 = dummy)

    for (int u = u0; u < u1; ++u) {
        const int n   = u >> 6;        // 64 m-tiles per n-stripe
        const int m   = u & 63;
        const int buf = u & 1;

        if (n != cur_n) {
            __syncthreads();
            load_A_async(tb + OFF_A, g_ts_h, n * BTN, tid);
            load_B_async(tb + OFF_B(buf), g_sq_h, m * BTM, tid);
            cp_commit();
            cp_wait0();
            cur_n = n;
        }
        if (u + 1 < u1 && ((u + 1) >> 6) == n) {
            load_B_async(tb + OFF_B(buf ^ 1), g_sq_h, ((u + 1) & 63) * BTM, tid);
        }
        cp_commit();
        cp_wait1();
        __syncthreads();

        const uint32_t aP = tb + OFF_A + aRow + offA;
        const uint32_t bP = tb + OFF_B(buf) + bRow + offB;

        uint32_t accC[4][8][2];
#pragma unroll
        for (int i = 0; i < 4; ++i)
#pragma unroll
            for (int cb = 0; cb < 8; ++cb) { accC[i][cb][0] = 0u; accC[i][cb][1] = 0u; }

#pragma unroll
        for (int kk = 0; kk < 8; ++kk) {
            const uint32_t ko = (uint32_t)(kk * 32);
            uint32_t a[4][4];
#pragma unroll
            for (int i = 0; i < 4; ++i)
                ldsm4(aP + i * (16 * SROW) + ko, a[i][0], a[i][1], a[i][2], a[i][3]);
#pragma unroll
            for (int j = 0; j < 4; ++j) {
                uint32_t b0, b1, b2, b3;
                ldsm4(bP + j * (16 * SROW) + ko, b0, b1, b2, b3);
#pragma unroll
                for (int i = 0; i < 4; ++i) {
                    mma16816h(accC[i][2 * j],     a[i], b0, b1);
                    mma16816h(accC[i][2 * j + 1], a[i], b2, b3);
                }
            }
            PREV_CHUNK(kk);            // previous unit's exp in the MMA shadow
        }

        // accP (stripe n_acc) fully consumed; flush only at stripe boundary
        if (n_acc >= 0 && n_acc != n) FLUSH(n_acc);
        n_acc = n;
#pragma unroll
        for (int i = 0; i < 4; ++i)
#pragma unroll
            for (int cb = 0; cb < 8; ++cb) {
                accP[i][cb][0] = accC[i][cb][0];
                accP[i][cb][1] = accC[i][cb][1];
            }
        __syncthreads();
    }

    // drain: last unit's accumulators, then final flush
#pragma unroll
    for (int kk = 0; kk < 8; ++kk) PREV_CHUNK(kk);
    if (n_acc >= 0) FLUSH(n_acc);
}

// ---------------- kernel 3: lse + masked loss (+ fused div) ----------------
__global__ void __launch_bounds__(256) k_final(const int* __restrict__ pmask,
                                               float* __restrict__ out) {
    __shared__ double s_loss[256];
    __shared__ float  s_pm[256];
    __shared__ int    s_last;
    const int tid = threadIdx.x;
    const int n   = blockIdx.x * 256 + tid;

    float d   = g_diag[n];
    float lse = SCALE + logf(g_rowsum[n]);
    float pm  = (float)pmask[n];

    s_loss[tid] = (double)(pm * (d - lse));
    s_pm[tid]   = pm;
    __syncthreads();
    for (int o = 128; o; o >>= 1) {
        if (tid < o) { s_loss[tid] += s_loss[tid + o]; s_pm[tid] += s_pm[tid + o]; }
        __syncthreads();
    }
    if (tid == 0) {
        atomicAdd(&g_acc[0], s_loss[0]);
        atomicAdd(&g_acc[1], (double)s_pm[0]);
        __threadfence();
        unsigned int v = atomicAdd(&g_cnt, 1u);
        s_last = (v == (unsigned int)(gridDim.x - 1)) ? 1 : 0;
    }
    __syncthreads();
    if (s_last && tid == 0)
        out[0] = (float)(-g_acc[0] / (g_acc[1] + 1e-6));
}

extern "C" void kernel_launch(void* const* d_in, const int* in_sizes, int n_in,
                              void* d_out, int out_size) {
    const float* ts = (const float*)d_in[0];
    const float* sq = (const float*)d_in[1];
    const int*   pm = (const int*)d_in[3];
    float* out = (float*)d_out;

    cudaFuncSetAttribute(k_main, cudaFuncAttributeMaxDynamicSharedMemorySize, SMEM_BYTES);

    k_norm<<<NN / 8, 256>>>(ts, sq);
    k_main<<<NCTA, 256, SMEM_BYTES>>>();
    k_final<<<NN / 256, 256>>>(pm, out);
}